// round 16
// baseline (speedup 1.0000x reference)
#include <cuda_runtime.h>
#include <cuda_fp16.h>
#include <cstdint>

// Problem constants
#define BB 4
#define NN 256
#define EE 63
#define DD 64
#define HH 128

// 16-pair chunks per b: 32896/16 = 2056. CTAs per b: 38 (152/4).
#define CHUNKS_PER_B 2056
#define GRID1 152
#define CTAS_PER_B 38
#define NTHREADS 480
#define NWARPS_CTA 15
#define WARPS_PER_B (CTAS_PER_B * NWARPS_CTA)   // 570

#define APITCH 136      // fp16 elems per row (272B = 17*16B: LDSM conflict-free)
#define W1PITCH 72      // (144B = 9*16B)

// SMEM layout (bytes)
#define OFF_W1   0           // 18432
#define OFF_W2   18432       // 34816 -> 53248
#define OFF_W3   53248       // 34816 -> 88064
#define OFF_P    88064       // 15*16*136*2 = 65280 -> 153344 (reused as ha/hb in finalize)
#define OFF_XS   153344      // 256*64*2 = 32768 -> 186112
#define OFF_B1   186112
#define OFF_B2   186624
#define OFF_B3   187136
#define OFF_ACCS 187648      // float accs[15][HH] = 7680 -> 195328
#define SMEM_BYTES 195328

// Scratch
__device__ float g_partial[GRID1 * HH];
__device__ unsigned int g_done = 0;

// ---------------- small helpers ----------------
__device__ __forceinline__ uint32_t pack_h2(float lo, float hi) {
    uint32_t r;
    asm("cvt.rn.f16x2.f32 %0, %1, %2;" : "=r"(r) : "f"(hi), "f"(lo));
    return r;
}
__device__ __forceinline__ uint32_t relu_h2(uint32_t v) {
    uint32_t r;
    asm("max.f16x2 %0, %1, %2;" : "=r"(r) : "r"(v), "r"(0u));
    return r;
}
__device__ __forceinline__ uint32_t mul_h2(uint32_t a, uint32_t b) {
    uint32_t r;
    asm("mul.rn.f16x2 %0, %1, %2;" : "=r"(r) : "r"(a), "r"(b));
    return r;
}
__device__ __forceinline__ uint32_t smaddr(const void* p) {
    uint32_t a;
    asm("{ .reg .u64 t; cvta.to.shared.u64 t, %1; cvt.u32.u64 %0, t; }"
        : "=r"(a) : "l"(p));
    return a;
}
__device__ __forceinline__ void ldsm4(uint32_t r[4], uint32_t addr) {
    asm volatile("ldmatrix.sync.aligned.m8n8.x4.shared.b16 {%0,%1,%2,%3}, [%4];"
                 : "=r"(r[0]), "=r"(r[1]), "=r"(r[2]), "=r"(r[3]) : "r"(addr));
}

// flat triangular index p in [0, 32896) -> (i, j), j >= i
__device__ __forceinline__ int2 pair_from_flat(int p) {
    int i = (int)(256.5f - sqrtf(65792.25f - 2.0f * (float)p));
    while (i * 256 - (i * (i - 1)) / 2 > p) --i;
    while ((i + 1) * 256 - ((i + 1) * i) / 2 <= p) ++i;
    int j = i + (p - (i * 256 - (i * (i - 1)) / 2));
    return make_int2(i, j);
}

// ---------------- HMMA m16n8k16 fp16 (f32 accum) ----------------
__device__ __forceinline__ void mma16816(float& c0, float& c1, float& c2, float& c3,
                                         uint32_t a0, uint32_t a1, uint32_t a2, uint32_t a3,
                                         uint32_t b0, uint32_t b1) {
    asm volatile("mma.sync.aligned.m16n8k16.row.col.f32.f16.f16.f32 "
                 "{%0,%1,%2,%3}, {%4,%5,%6,%7}, {%8,%9}, {%0,%1,%2,%3};"
                 : "+f"(c0), "+f"(c1), "+f"(c2), "+f"(c3)
                 : "r"(a0), "r"(a1), "r"(a2), "r"(a3), "r"(b0), "r"(b1));
}

__device__ __forceinline__ void bias_init(const float* __restrict__ bias, int tig,
                                          float C[16][4]) {
#pragma unroll
    for (int nt = 0; nt < 16; nt++) {
        float2 bv = *(const float2*)(bias + nt * 8 + 2 * tig);
        C[nt][0] = bv.x; C[nt][1] = bv.y;
        C[nt][2] = bv.x; C[nt][3] = bv.y;
    }
}

__device__ __forceinline__ void pack_a(const float C[16][4], uint32_t A[8][4]) {
#pragma unroll
    for (int ks = 0; ks < 8; ks++) {
        const float* e = C[2 * ks];
        const float* o = C[2 * ks + 1];
        A[ks][0] = relu_h2(pack_h2(e[0], e[1]));
        A[ks][1] = relu_h2(pack_h2(e[2], e[3]));
        A[ks][2] = relu_h2(pack_h2(o[0], o[1]));
        A[ks][3] = relu_h2(pack_h2(o[2], o[3]));
    }
}

// one K=128 layer: A in regs, B (weights) via LDSM from SMEM
__device__ __forceinline__ void layer_reg(const uint32_t A[8][4], uint32_t aW,
                                          float C[16][4]) {
#pragma unroll
    for (int ks = 0; ks < 8; ks++) {
#pragma unroll
        for (int ntp = 0; ntp < 8; ntp++) {
            uint32_t b[4];
            ldsm4(b, aW + (uint32_t)(ntp * 16 * APITCH + ks * 16) * 2);
            mma16816(C[2*ntp][0], C[2*ntp][1], C[2*ntp][2], C[2*ntp][3],
                     A[ks][0], A[ks][1], A[ks][2], A[ks][3], b[0], b[1]);
            mma16816(C[2*ntp+1][0], C[2*ntp+1][1], C[2*ntp+1][2], C[2*ntp+1][3],
                     A[ks][0], A[ks][1], A[ks][2], A[ks][3], b[2], b[3]);
        }
    }
}

// build the 16xDD p tile from SMEM-resident x slice (fp16)
__device__ __forceinline__ void build_p(const __half* __restrict__ xs, int P0,
                                        __half* __restrict__ prow, int lane) {
    int m = lane >> 1;
    int kh = (lane & 1) * 32;
    int2 ij = pair_from_flat(P0 + m);
    const uint4* xi = (const uint4*)(xs + ij.x * DD + kh);
    const uint4* xj = (const uint4*)(xs + ij.y * DD + kh);
    uint4* row = (uint4*)(prow + m * APITCH + kh);
#pragma unroll
    for (int q = 0; q < 4; q++) {
        uint4 a = xi[q], c = xj[q];
        uint4 r;
        r.x = mul_h2(a.x, c.x); r.y = mul_h2(a.y, c.y);
        r.z = mul_h2(a.z, c.z); r.w = mul_h2(a.w, c.w);
        row[q] = r;
    }
}

__device__ void load_w(const float* __restrict__ W, int K, __half* dst, int pitch, int tid) {
    for (int idx = tid; idx < K * HH; idx += NTHREADS) {
        int f = idx & 127, k = idx >> 7;
        dst[f * pitch + k] = __float2half(W[k * HH + f]);
    }
}

// ---------------- The single fused kernel ----------------
__global__ void __launch_bounds__(NTHREADS, 1)
pair_mlp_kernel(const int* __restrict__ xcat32, const float* __restrict__ xfeat,
                const float* __restrict__ emb,
                const float* __restrict__ W1, const float* __restrict__ b1,
                const float* __restrict__ W2, const float* __restrict__ b2,
                const float* __restrict__ W3, const float* __restrict__ b3,
                const float* __restrict__ D1, const float* __restrict__ c1,
                const float* __restrict__ D2, const float* __restrict__ c2,
                const float* __restrict__ D3, const float* __restrict__ c3,
                float* __restrict__ out) {
    extern __shared__ char sm[];
    __half* W1s = (__half*)(sm + OFF_W1);
    __half* W2s = (__half*)(sm + OFF_W2);
    __half* W3s = (__half*)(sm + OFF_W3);
    __half* pbuf = (__half*)(sm + OFF_P);
    __half* xs  = (__half*)(sm + OFF_XS);
    float* b1s = (float*)(sm + OFF_B1);
    float* b2s = (float*)(sm + OFF_B2);
    float* b3s = (float*)(sm + OFF_B3);
    float* accs = (float*)(sm + OFF_ACCS);   // [15 warps][HH]
    __shared__ unsigned s_last;

    const int tid = threadIdx.x;
    const int warp = tid >> 5, lane = tid & 31;
    const int g = lane >> 2, tig = lane & 3;
    const int myb = blockIdx.x / CTAS_PER_B;
    const int cidx = blockIdx.x - myb * CTAS_PER_B;
    __half* prow = pbuf + warp * 16 * APITCH;

    // ---- prologue: weights + x slice for this b into SMEM ----
    load_w(W1, DD, W1s, W1PITCH, tid);
    load_w(W2, HH, W2s, APITCH, tid);
    load_w(W3, HH, W3s, APITCH, tid);
    if (tid < 128) { b1s[tid] = b1[tid]; b2s[tid] = b2[tid]; b3s[tid] = b3[tid]; }
    for (int idx = tid; idx < NWARPS_CTA * HH; idx += NTHREADS) accs[idx] = 0.f;
    {
        bool is64 = (xcat32[1] == 0) && (xcat32[3] == 0) && (xcat32[5] == 0) &&
                    (xcat32[7] == 0) && (xcat32[9] == 0) && (xcat32[11] == 0);
        for (int idx = tid; idx < NN * DD; idx += NTHREADS) {
            int row = idx >> 6, d = idx & 63;
            int grow = myb * NN + row;
            int ci = is64 ? xcat32[grow * 2] : xcat32[grow];
            float v = (d < EE) ? emb[ci * EE + d] : xfeat[grow];
            xs[idx] = __float2half(v);
        }
    }
    __syncthreads();

    // per-lane LDSM base addresses
    const int lr = lane & 7;
    const int bq_row = 8 * ((lane >> 4) & 1) + lr;
    const int bq_kh  = 8 * ((lane >> 3) & 1);
    const uint32_t aW1 = smaddr(W1s) + (uint32_t)(bq_row * W1PITCH + bq_kh) * 2;
    const uint32_t aW2 = smaddr(W2s) + (uint32_t)(bq_row * APITCH + bq_kh) * 2;
    const uint32_t aW3 = smaddr(W3s) + (uint32_t)(bq_row * APITCH + bq_kh) * 2;
    const int aq_row = 8 * ((lane >> 3) & 1) + lr;
    const int aq_kh  = 8 * ((lane >> 4) & 1);
    const uint32_t aP = smaddr(prow) + (uint32_t)(aq_row * APITCH + aq_kh) * 2;

    // contiguous chunk range within this b for this warp (max 4 chunks)
    const int wb = cidx * NWARPS_CTA + warp;
    const int cstart = (int)(((long long)wb * CHUNKS_PER_B) / WARPS_PER_B);
    const int cend   = (int)(((long long)(wb + 1) * CHUNKS_PER_B) / WARPS_PER_B);

    float C[16][4];
    uint32_t A[8][4];
    float* ap = accs + warp * HH + 2 * tig;

    build_p(xs, cstart * 16, prow, lane);

    for (int c = cstart; c < cend; c++) {
        int P0 = c * 16;
        __syncwarp();

        // ---- Layer 1 (K=64) ----
        bias_init(b1s, tig, C);
#pragma unroll
        for (int ks = 0; ks < 4; ks++) {
            uint32_t a[4];
            ldsm4(a, aP + (uint32_t)(ks * 16) * 2);
#pragma unroll
            for (int ntp = 0; ntp < 8; ntp++) {
                uint32_t bfr[4];
                ldsm4(bfr, aW1 + (uint32_t)(ntp * 16 * W1PITCH + ks * 16) * 2);
                mma16816(C[2*ntp][0], C[2*ntp][1], C[2*ntp][2], C[2*ntp][3],
                         a[0], a[1], a[2], a[3], bfr[0], bfr[1]);
                mma16816(C[2*ntp+1][0], C[2*ntp+1][1], C[2*ntp+1][2], C[2*ntp+1][3],
                         a[0], a[1], a[2], a[3], bfr[2], bfr[3]);
            }
        }

        // ---- Layer 2 prep; prefetch-build next chunk's p tile ----
        pack_a(C, A);
        if (c + 1 < cend) build_p(xs, (c + 1) * 16, prow, lane);
        bias_init(b2s, tig, C);
        layer_reg(A, aW2, C);

        // ---- Layer 3 ----
        pack_a(C, A);
        bias_init(b3s, tig, C);
        layer_reg(A, aW3, C);

        // ---- epilogue: relu + multiplicity + pooled reduce (per chunk) ----
        int2 ija = pair_from_flat(P0 + g);
        int2 ijb = pair_from_flat(P0 + g + 8);
        float wa = (ija.x == ija.y) ? 1.f : 2.f;
        float wb2 = (ijb.x == ijb.y) ? 1.f : 2.f;
#pragma unroll
        for (int nt = 0; nt < 16; nt++) {
            float s0 = wa * fmaxf(C[nt][0], 0.f) + wb2 * fmaxf(C[nt][2], 0.f);
            float s1 = wa * fmaxf(C[nt][1], 0.f) + wb2 * fmaxf(C[nt][3], 0.f);
            s0 += __shfl_xor_sync(0xffffffffu, s0, 4);
            s0 += __shfl_xor_sync(0xffffffffu, s0, 8);
            s0 += __shfl_xor_sync(0xffffffffu, s0, 16);
            s1 += __shfl_xor_sync(0xffffffffu, s1, 4);
            s1 += __shfl_xor_sync(0xffffffffu, s1, 8);
            s1 += __shfl_xor_sync(0xffffffffu, s1, 16);
            if (lane < 4) {
                ap[nt * 8]     += s0;
                ap[nt * 8 + 1] += s1;
            }
        }
    }

    __syncthreads();
    for (int idx = tid; idx < HH; idx += NTHREADS) {
        float s = 0.f;
#pragma unroll
        for (int w = 0; w < NWARPS_CTA; w++) s += accs[w * HH + idx];
        g_partial[blockIdx.x * HH + idx] = s;
    }

    // ---- last-CTA finalize (deterministic: fixed-order reduction) ----
    __threadfence();
    if (tid == 0) {
        unsigned old = atomicAdd(&g_done, 1u);
        s_last = (old == GRID1 - 1) ? 1u : 0u;
    }
    __syncthreads();
    if (!s_last) return;
    __threadfence();

    float* ha = (float*)(sm + OFF_P);
    float* hb = ha + BB * HH;
    for (int idx = tid; idx < BB * HH; idx += NTHREADS) {
        int b = idx >> 7, f = idx & 127;
        float s = 0.f;
        for (int cc = 0; cc < CTAS_PER_B; cc++)
            s += g_partial[(b * CTAS_PER_B + cc) * HH + f];
        ha[idx] = fmaxf(s * (1.0f / (float)(NN * NN)), 0.f);
    }
    __syncthreads();
    for (int idx = tid; idx < BB * HH; idx += NTHREADS) {
        int b = idx >> 7, f = idx & 127;
        float v = c1[f];
        for (int k = 0; k < HH; k++) v += ha[b * HH + k] * D1[k * HH + f];
        hb[idx] = fmaxf(v, 0.f);
    }
    __syncthreads();
    for (int idx = tid; idx < BB * HH; idx += NTHREADS) {
        int b = idx >> 7, f = idx & 127;
        float v = c2[f];
        for (int k = 0; k < HH; k++) v += hb[b * HH + k] * D2[k * HH + f];
        ha[idx] = fmaxf(v, 0.f);
    }
    __syncthreads();
    if (tid < BB) {
        float o = c3[0];
        for (int k = 0; k < HH; k++) o += ha[tid * HH + k] * D3[k];
        out[tid] = o;
    }
    if (tid == 0) g_done = 0;    // reset for next graph replay
}

// ---------------- Launch ----------------
extern "C" void kernel_launch(void* const* d_in, const int* in_sizes, int n_in,
                              void* d_out, int out_size) {
    const int*   xcat  = (const int*)d_in[0];
    const float* xfeat = (const float*)d_in[1];
    const float* emb   = (const float*)d_in[2];
    const float* W1 = (const float*)d_in[3];
    const float* b1 = (const float*)d_in[4];
    const float* W2 = (const float*)d_in[5];
    const float* b2 = (const float*)d_in[6];
    const float* W3 = (const float*)d_in[7];
    const float* b3 = (const float*)d_in[8];
    const float* D1 = (const float*)d_in[9];
    const float* c1 = (const float*)d_in[10];
    const float* D2 = (const float*)d_in[11];
    const float* c2 = (const float*)d_in[12];
    const float* D3 = (const float*)d_in[13];
    const float* c3 = (const float*)d_in[14];
    float* out = (float*)d_out;

    cudaFuncSetAttribute(pair_mlp_kernel,
                         cudaFuncAttributeMaxDynamicSharedMemorySize, SMEM_BYTES);

    pair_mlp_kernel<<<GRID1, NTHREADS, SMEM_BYTES>>>(
        xcat, xfeat, emb, W1, b1, W2, b2, W3, b3,
        D1, c1, D2, c2, D3, c3, out);
}

// round 17
// speedup vs baseline: 1.0940x; 1.0940x over previous
#include <cuda_runtime.h>
#include <cuda_fp16.h>
#include <cstdint>

// Problem constants
#define BB 4
#define NN 256
#define EE 63
#define DD 64
#define HH 128

// 16-pair chunks per b: 32896/16 = 2056. CTAs per b: 38 (152/4).
#define CHUNKS_PER_B 2056
#define GRID1 152
#define CTAS_PER_B 38
#define NTHREADS 384
#define NWARPS_CTA 12
#define WARPS_PER_B (CTAS_PER_B * NWARPS_CTA)   // 456

#define APITCH 136      // fp16 elems per row (272B = 17*16B: LDSM conflict-free)
#define W1PITCH 72      // (144B = 9*16B)

// SMEM layout (bytes)
#define OFF_W1   0           // 18432
#define OFF_W2   18432       // 34816 -> 53248
#define OFF_W3   53248       // 34816 -> 88064
#define OFF_P    88064       // 12*16*136*2 = 52224 -> 140288 (reused as ha/hb in finalize)
#define OFF_XS   140288      // 256*64*2 = 32768 -> 173056
#define OFF_B1   173056
#define OFF_B2   173568
#define OFF_B3   174080
#define OFF_ACCS 174592      // float accs[12][HH] = 6144 -> 180736
#define SMEM_BYTES 180736

// Scratch
__device__ float g_partial[GRID1 * HH];
__device__ unsigned int g_done = 0;

// ---------------- small helpers ----------------
__device__ __forceinline__ uint32_t pack_h2(float lo, float hi) {
    uint32_t r;
    asm("cvt.rn.f16x2.f32 %0, %1, %2;" : "=r"(r) : "f"(hi), "f"(lo));
    return r;
}
__device__ __forceinline__ uint32_t relu_h2(uint32_t v) {
    uint32_t r;
    asm("max.f16x2 %0, %1, %2;" : "=r"(r) : "r"(v), "r"(0u));
    return r;
}
__device__ __forceinline__ uint32_t mul_h2(uint32_t a, uint32_t b) {
    uint32_t r;
    asm("mul.rn.f16x2 %0, %1, %2;" : "=r"(r) : "r"(a), "r"(b));
    return r;
}
__device__ __forceinline__ uint32_t smaddr(const void* p) {
    uint32_t a;
    asm("{ .reg .u64 t; cvta.to.shared.u64 t, %1; cvt.u32.u64 %0, t; }"
        : "=r"(a) : "l"(p));
    return a;
}
__device__ __forceinline__ void ldsm4(uint32_t r[4], uint32_t addr) {
    asm volatile("ldmatrix.sync.aligned.m8n8.x4.shared.b16 {%0,%1,%2,%3}, [%4];"
                 : "=r"(r[0]), "=r"(r[1]), "=r"(r[2]), "=r"(r[3]) : "r"(addr));
}

// flat triangular index p in [0, 32896) -> (i, j), j >= i
__device__ __forceinline__ int2 pair_from_flat(int p) {
    int i = (int)(256.5f - sqrtf(65792.25f - 2.0f * (float)p));
    while (i * 256 - (i * (i - 1)) / 2 > p) --i;
    while ((i + 1) * 256 - ((i + 1) * i) / 2 <= p) ++i;
    int j = i + (p - (i * 256 - (i * (i - 1)) / 2));
    return make_int2(i, j);
}

// ---------------- HMMA m16n8k16 fp16 (f32 accum) ----------------
__device__ __forceinline__ void mma16816(float& c0, float& c1, float& c2, float& c3,
                                         uint32_t a0, uint32_t a1, uint32_t a2, uint32_t a3,
                                         uint32_t b0, uint32_t b1) {
    asm volatile("mma.sync.aligned.m16n8k16.row.col.f32.f16.f16.f32 "
                 "{%0,%1,%2,%3}, {%4,%5,%6,%7}, {%8,%9}, {%0,%1,%2,%3};"
                 : "+f"(c0), "+f"(c1), "+f"(c2), "+f"(c3)
                 : "r"(a0), "r"(a1), "r"(a2), "r"(a3), "r"(b0), "r"(b1));
}

__device__ __forceinline__ void bias_init(const float* __restrict__ bias, int tig,
                                          float C[16][4]) {
#pragma unroll
    for (int nt = 0; nt < 16; nt++) {
        float2 bv = *(const float2*)(bias + nt * 8 + 2 * tig);
        C[nt][0] = bv.x; C[nt][1] = bv.y;
        C[nt][2] = bv.x; C[nt][3] = bv.y;
    }
}

__device__ __forceinline__ void pack_a(const float C[16][4], uint32_t A[8][4]) {
#pragma unroll
    for (int ks = 0; ks < 8; ks++) {
        const float* e = C[2 * ks];
        const float* o = C[2 * ks + 1];
        A[ks][0] = relu_h2(pack_h2(e[0], e[1]));
        A[ks][1] = relu_h2(pack_h2(e[2], e[3]));
        A[ks][2] = relu_h2(pack_h2(o[0], o[1]));
        A[ks][3] = relu_h2(pack_h2(o[2], o[3]));
    }
}

// one K=128 layer: A in regs, B (weights) via LDSM from SMEM
__device__ __forceinline__ void layer_reg(const uint32_t A[8][4], uint32_t aW,
                                          float C[16][4]) {
#pragma unroll
    for (int ks = 0; ks < 8; ks++) {
#pragma unroll
        for (int ntp = 0; ntp < 8; ntp++) {
            uint32_t b[4];
            ldsm4(b, aW + (uint32_t)(ntp * 16 * APITCH + ks * 16) * 2);
            mma16816(C[2*ntp][0], C[2*ntp][1], C[2*ntp][2], C[2*ntp][3],
                     A[ks][0], A[ks][1], A[ks][2], A[ks][3], b[0], b[1]);
            mma16816(C[2*ntp+1][0], C[2*ntp+1][1], C[2*ntp+1][2], C[2*ntp+1][3],
                     A[ks][0], A[ks][1], A[ks][2], A[ks][3], b[2], b[3]);
        }
    }
}

// build the 16xDD p tile from SMEM-resident x slice (fp16)
__device__ __forceinline__ void build_p(const __half* __restrict__ xs, int P0,
                                        __half* __restrict__ prow, int lane) {
    int m = lane >> 1;
    int kh = (lane & 1) * 32;
    int2 ij = pair_from_flat(P0 + m);
    const uint4* xi = (const uint4*)(xs + ij.x * DD + kh);
    const uint4* xj = (const uint4*)(xs + ij.y * DD + kh);
    uint4* row = (uint4*)(prow + m * APITCH + kh);
#pragma unroll
    for (int q = 0; q < 4; q++) {
        uint4 a = xi[q], c = xj[q];
        uint4 r;
        r.x = mul_h2(a.x, c.x); r.y = mul_h2(a.y, c.y);
        r.z = mul_h2(a.z, c.z); r.w = mul_h2(a.w, c.w);
        row[q] = r;
    }
}

__device__ __forceinline__ void flush_acc(float acc[16][2], float* __restrict__ accs,
                                          int warp, int lane, int tig) {
    float* ap = accs + warp * HH + 2 * tig;
#pragma unroll
    for (int nt = 0; nt < 16; nt++) {
        float s0 = acc[nt][0], s1 = acc[nt][1];
        s0 += __shfl_xor_sync(0xffffffffu, s0, 4);
        s0 += __shfl_xor_sync(0xffffffffu, s0, 8);
        s0 += __shfl_xor_sync(0xffffffffu, s0, 16);
        s1 += __shfl_xor_sync(0xffffffffu, s1, 4);
        s1 += __shfl_xor_sync(0xffffffffu, s1, 8);
        s1 += __shfl_xor_sync(0xffffffffu, s1, 16);
        if (lane < 4) {
            ap[nt * 8]     = s0;
            ap[nt * 8 + 1] = s1;
        }
    }
}

__device__ void load_w(const float* __restrict__ W, int K, __half* dst, int pitch, int tid) {
    for (int idx = tid; idx < K * HH; idx += NTHREADS) {
        int f = idx & 127, k = idx >> 7;
        dst[f * pitch + k] = __float2half(W[k * HH + f]);
    }
}

// ---------------- The single fused kernel ----------------
__global__ void __launch_bounds__(NTHREADS, 1)
pair_mlp_kernel(const int* __restrict__ xcat32, const float* __restrict__ xfeat,
                const float* __restrict__ emb,
                const float* __restrict__ W1, const float* __restrict__ b1,
                const float* __restrict__ W2, const float* __restrict__ b2,
                const float* __restrict__ W3, const float* __restrict__ b3,
                const float* __restrict__ D1, const float* __restrict__ c1,
                const float* __restrict__ D2, const float* __restrict__ c2,
                const float* __restrict__ D3, const float* __restrict__ c3,
                float* __restrict__ out) {
    extern __shared__ char sm[];
    __half* W1s = (__half*)(sm + OFF_W1);
    __half* W2s = (__half*)(sm + OFF_W2);
    __half* W3s = (__half*)(sm + OFF_W3);
    __half* pbuf = (__half*)(sm + OFF_P);
    __half* xs  = (__half*)(sm + OFF_XS);
    float* b1s = (float*)(sm + OFF_B1);
    float* b2s = (float*)(sm + OFF_B2);
    float* b3s = (float*)(sm + OFF_B3);
    float* accs = (float*)(sm + OFF_ACCS);   // [12 warps][HH]
    __shared__ unsigned s_last;

    const int tid = threadIdx.x;
    const int warp = tid >> 5, lane = tid & 31;
    const int g = lane >> 2, tig = lane & 3;
    const int myb = blockIdx.x / CTAS_PER_B;
    const int cidx = blockIdx.x - myb * CTAS_PER_B;
    __half* prow = pbuf + warp * 16 * APITCH;

    // ---- prologue: weights + x slice for this b into SMEM ----
    load_w(W1, DD, W1s, W1PITCH, tid);
    load_w(W2, HH, W2s, APITCH, tid);
    load_w(W3, HH, W3s, APITCH, tid);
    if (tid < 128) { b1s[tid] = b1[tid]; b2s[tid] = b2[tid]; b3s[tid] = b3[tid]; }
    {
        bool is64 = (xcat32[1] == 0) && (xcat32[3] == 0) && (xcat32[5] == 0) &&
                    (xcat32[7] == 0) && (xcat32[9] == 0) && (xcat32[11] == 0);
        for (int idx = tid; idx < NN * DD; idx += NTHREADS) {
            int row = idx >> 6, d = idx & 63;
            int grow = myb * NN + row;
            int ci = is64 ? xcat32[grow * 2] : xcat32[grow];
            float v = (d < EE) ? emb[ci * EE + d] : xfeat[grow];
            xs[idx] = __float2half(v);
        }
    }
    __syncthreads();

    // per-lane LDSM base addresses
    const int lr = lane & 7;
    const int bq_row = 8 * ((lane >> 4) & 1) + lr;
    const int bq_kh  = 8 * ((lane >> 3) & 1);
    const uint32_t aW1 = smaddr(W1s) + (uint32_t)(bq_row * W1PITCH + bq_kh) * 2;
    const uint32_t aW2 = smaddr(W2s) + (uint32_t)(bq_row * APITCH + bq_kh) * 2;
    const uint32_t aW3 = smaddr(W3s) + (uint32_t)(bq_row * APITCH + bq_kh) * 2;
    const int aq_row = 8 * ((lane >> 3) & 1) + lr;
    const int aq_kh  = 8 * ((lane >> 4) & 1);
    const uint32_t aP = smaddr(prow) + (uint32_t)(aq_row * APITCH + aq_kh) * 2;

    // contiguous chunk range within this b for this warp
    const int wb = cidx * NWARPS_CTA + warp;
    const int cstart = (int)(((long long)wb * CHUNKS_PER_B) / WARPS_PER_B);
    const int cend   = (int)(((long long)(wb + 1) * CHUNKS_PER_B) / WARPS_PER_B);

    float C[16][4];
    uint32_t A[8][4];
    float acc[16][2];
#pragma unroll
    for (int nt = 0; nt < 16; nt++) { acc[nt][0] = 0.f; acc[nt][1] = 0.f; }

    build_p(xs, cstart * 16, prow, lane);

    for (int c = cstart; c < cend; c++) {
        int P0 = c * 16;
        __syncwarp();

        // ---- Layer 1 (K=64): hoist ALL four A-fragment LDSMs into the dead
        //      A[0..3] registers (zero extra pressure), overlapping their
        //      latency with the whole B-load/MMA stream of the layer. ----
        bias_init(b1s, tig, C);
#pragma unroll
        for (int ks = 0; ks < 4; ks++)
            ldsm4(A[ks], aP + (uint32_t)(ks * 16) * 2);
#pragma unroll
        for (int ks = 0; ks < 4; ks++) {
#pragma unroll
            for (int ntp = 0; ntp < 8; ntp++) {
                uint32_t bfr[4];
                ldsm4(bfr, aW1 + (uint32_t)(ntp * 16 * W1PITCH + ks * 16) * 2);
                mma16816(C[2*ntp][0], C[2*ntp][1], C[2*ntp][2], C[2*ntp][3],
                         A[ks][0], A[ks][1], A[ks][2], A[ks][3], bfr[0], bfr[1]);
                mma16816(C[2*ntp+1][0], C[2*ntp+1][1], C[2*ntp+1][2], C[2*ntp+1][3],
                         A[ks][0], A[ks][1], A[ks][2], A[ks][3], bfr[2], bfr[3]);
            }
        }

        // ---- Layer 2 prep; prefetch-build next chunk's p tile ----
        pack_a(C, A);
        if (c + 1 < cend) build_p(xs, (c + 1) * 16, prow, lane);
        bias_init(b2s, tig, C);
        layer_reg(A, aW2, C);

        // ---- Layer 3 ----
        pack_a(C, A);
        bias_init(b3s, tig, C);
        layer_reg(A, aW3, C);

        // ---- weighted accumulate into register pool ----
        int2 ija = pair_from_flat(P0 + g);
        int2 ijb = pair_from_flat(P0 + g + 8);
        float wa = (ija.x == ija.y) ? 1.f : 2.f;
        float wb2 = (ijb.x == ijb.y) ? 1.f : 2.f;
#pragma unroll
        for (int nt = 0; nt < 16; nt++) {
            acc[nt][0] += wa * fmaxf(C[nt][0], 0.f) + wb2 * fmaxf(C[nt][2], 0.f);
            acc[nt][1] += wa * fmaxf(C[nt][1], 0.f) + wb2 * fmaxf(C[nt][3], 0.f);
        }
    }
    flush_acc(acc, accs, warp, lane, tig);

    __syncthreads();
    for (int idx = tid; idx < HH; idx += NTHREADS) {
        float s = 0.f;
#pragma unroll
        for (int w = 0; w < NWARPS_CTA; w++) s += accs[w * HH + idx];
        g_partial[blockIdx.x * HH + idx] = s;
    }

    // ---- last-CTA finalize (deterministic: fixed-order reduction) ----
    __threadfence();
    if (tid == 0) {
        unsigned old = atomicAdd(&g_done, 1u);
        s_last = (old == GRID1 - 1) ? 1u : 0u;
    }
    __syncthreads();
    if (!s_last) return;
    __threadfence();

    float* ha = (float*)(sm + OFF_P);
    float* hb = ha + BB * HH;
    for (int idx = tid; idx < BB * HH; idx += NTHREADS) {
        int b = idx >> 7, f = idx & 127;
        float s = 0.f;
        for (int cc = 0; cc < CTAS_PER_B; cc++)
            s += g_partial[(b * CTAS_PER_B + cc) * HH + f];
        ha[idx] = fmaxf(s * (1.0f / (float)(NN * NN)), 0.f);
    }
    __syncthreads();
    for (int idx = tid; idx < BB * HH; idx += NTHREADS) {
        int b = idx >> 7, f = idx & 127;
        float v = c1[f];
        for (int k = 0; k < HH; k++) v += ha[b * HH + k] * D1[k * HH + f];
        hb[idx] = fmaxf(v, 0.f);
    }
    __syncthreads();
    for (int idx = tid; idx < BB * HH; idx += NTHREADS) {
        int b = idx >> 7, f = idx & 127;
        float v = c2[f];
        for (int k = 0; k < HH; k++) v += hb[b * HH + k] * D2[k * HH + f];
        ha[idx] = fmaxf(v, 0.f);
    }
    __syncthreads();
    if (tid < BB) {
        float o = c3[0];
        for (int k = 0; k < HH; k++) o += ha[tid * HH + k] * D3[k];
        out[tid] = o;
    }
    if (tid == 0) g_done = 0;    // reset for next graph replay
}

// ---------------- Launch ----------------
extern "C" void kernel_launch(void* const* d_in, const int* in_sizes, int n_in,
                              void* d_out, int out_size) {
    const int*   xcat  = (const int*)d_in[0];
    const float* xfeat = (const float*)d_in[1];
    const float* emb   = (const float*)d_in[2];
    const float* W1 = (const float*)d_in[3];
    const float* b1 = (const float*)d_in[4];
    const float* W2 = (const float*)d_in[5];
    const float* b2 = (const float*)d_in[6];
    const float* W3 = (const float*)d_in[7];
    const float* b3 = (const float*)d_in[8];
    const float* D1 = (const float*)d_in[9];
    const float* c1 = (const float*)d_in[10];
    const float* D2 = (const float*)d_in[11];
    const float* c2 = (const float*)d_in[12];
    const float* D3 = (const float*)d_in[13];
    const float* c3 = (const float*)d_in[14];
    float* out = (float*)d_out;

    cudaFuncSetAttribute(pair_mlp_kernel,
                         cudaFuncAttributeMaxDynamicSharedMemorySize, SMEM_BYTES);

    pair_mlp_kernel<<<GRID1, NTHREADS, SMEM_BYTES>>>(
        xcat, xfeat, emb, W1, b1, W2, b2, W3, b3,
        D1, c1, D2, c2, D3, c3, out);
}